// round 4
// baseline (speedup 1.0000x reference)
#include <cuda_runtime.h>
#include <cstdint>

#define HD 512
#define DD 64
#define ROWS 32
#define NT 512

// Transposed weights (filled by transpose kernels each launch).
__device__ float g_W1T[HD * HD];   // W1T[k][c] = W1[c][k]
__device__ float g_W2T[HD * HD];   // W2T[k][c] = W2[c][k]
__device__ float g_W0T[HD * DD];   // W0T[h][d] = W0[d][h]

__device__ __forceinline__ float4 ld4(const float* __restrict__ p) {
    return *reinterpret_cast<const float4*>(p);
}

__device__ __forceinline__ uint64_t pk(float lo, float hi) {
    uint64_t r;
    asm("mov.b64 %0, {%1, %2};" : "=l"(r) : "f"(lo), "f"(hi));
    return r;
}
__device__ __forceinline__ float2 upk(uint64_t v) {
    float2 r;
    asm("mov.b64 {%0, %1}, %2;" : "=f"(r.x), "=f"(r.y) : "l"(v));
    return r;
}
__device__ __forceinline__ void ffma2(uint64_t& d, uint64_t a, uint64_t b) {
    asm("fma.rn.f32x2 %0, %1, %2, %0;" : "+l"(d) : "l"(a), "l"(b));
}

// Tiled transpose: in[R][C] -> out[C][R]
__global__ void tr_kernel(const float* __restrict__ in, float* __restrict__ out,
                          int R, int C) {
    __shared__ float t[32][33];
    int x = blockIdx.x * 32 + threadIdx.x;
    int y = blockIdx.y * 32 + threadIdx.y;
#pragma unroll
    for (int dy = 0; dy < 32; dy += 8)
        if (y + dy < R && x < C)
            t[threadIdx.y + dy][threadIdx.x] = in[(y + dy) * C + x];
    __syncthreads();
    int xo = blockIdx.y * 32 + threadIdx.x;
    int yo = blockIdx.x * 32 + threadIdx.y;
#pragma unroll
    for (int dy = 0; dy < 32; dy += 8)
        if (yo + dy < C && xo < R)
            out[(yo + dy) * R + xo] = t[threadIdx.x][threadIdx.y + dy];
}

// Packed-f32x2 GEMM tile: 8 rows (rg+4i) x 4 scalar cols (c4..c4+3).
// acc[i][c] is an f32x2 pair {even-k partial, odd-k partial}.
// prev: smem [ROWS][K] (broadcast loads); W: global [K][HD] coalesced.
template<int K>
__device__ __forceinline__ void gemm2(
    const float* __restrict__ prev, const float* __restrict__ W,
    uint64_t acc[8][4], int c4, int rg)
{
#pragma unroll
    for (int i = 0; i < 8; i++)
#pragma unroll
        for (int c = 0; c < 4; c++)
            acc[i][c] = 0ULL;   // {0.f, 0.f}

#pragma unroll 2
    for (int k = 0; k < K; k += 4) {
        float4 wr0 = ld4(&W[(k + 0) * HD + c4]);
        float4 wr1 = ld4(&W[(k + 1) * HD + c4]);
        float4 wr2 = ld4(&W[(k + 2) * HD + c4]);
        float4 wr3 = ld4(&W[(k + 3) * HD + c4]);
        uint64_t P0[4] = { pk(wr0.x, wr1.x), pk(wr0.y, wr1.y),
                           pk(wr0.z, wr1.z), pk(wr0.w, wr1.w) };
        uint64_t P1[4] = { pk(wr2.x, wr3.x), pk(wr2.y, wr3.y),
                           pk(wr2.z, wr3.z), pk(wr2.w, wr3.w) };
#pragma unroll
        for (int i = 0; i < 8; i++) {
            ulonglong2 av = *reinterpret_cast<const ulonglong2*>(
                &prev[(rg + 4 * i) * K + k]);   // {a[k],a[k+1]},{a[k+2],a[k+3]}
#pragma unroll
            for (int c = 0; c < 4; c++) ffma2(acc[i][c], av.x, P0[c]);
#pragma unroll
            for (int c = 0; c < 4; c++) ffma2(acc[i][c], av.y, P1[c]);
        }
    }
}

__device__ __forceinline__ float hsum(uint64_t v) {
    float2 f = upk(v);
    return f.x + f.y;
}

__global__ void __launch_bounds__(NT, 1)
hnn_fused_kernel(
    const float* __restrict__ x,
    const float* __restrict__ W0, const float* __restrict__ b0,
    const float* __restrict__ W1, const float* __restrict__ b1,
    const float* __restrict__ W2, const float* __restrict__ b2,
    const float* __restrict__ W3,
    float* __restrict__ out)
{
    extern __shared__ float smem[];
    float* h0   = smem;                 // [32][512]
    float* h1   = smem + ROWS * HD;     // [32][512]
    float* dbuf = smem + 2 * ROWS * HD; // [32][512], first 2048 floats alias xs
    float* xs   = dbuf;                 // [32][64]

    const int tid = threadIdx.x;
    const int cl = tid & 127;           // float4-col index (128 of them)
    const int c4 = cl * 4;              // scalar col base
    const int rg = tid >> 7;            // rows rg + 4*i, i=0..7
    const long base_row = (long)blockIdx.x * ROWS;

    // load x tile: 512 float4, one per thread (coalesced)
    {
        const float4* xg = reinterpret_cast<const float4*>(x + base_row * DD);
        reinterpret_cast<float4*>(xs)[tid] = xg[tid];
    }
    __syncthreads();

    uint64_t acc[8][4];

    // L0: h0 = tanh(xs @ W0 + b0)
    gemm2<DD>(xs, W0, acc, c4, rg);
    {
        float4 bb = ld4(&b0[c4]);
#pragma unroll
        for (int i = 0; i < 8; i++) {
            float4 v;
            v.x = tanhf(hsum(acc[i][0]) + bb.x);
            v.y = tanhf(hsum(acc[i][1]) + bb.y);
            v.z = tanhf(hsum(acc[i][2]) + bb.z);
            v.w = tanhf(hsum(acc[i][3]) + bb.w);
            *reinterpret_cast<float4*>(&h0[(rg + 4 * i) * HD + c4]) = v;
        }
    }
    __syncthreads();

    // L1: h1 = tanh(h0 @ W1 + b1)
    gemm2<HD>(h0, W1, acc, c4, rg);
    {
        float4 bb = ld4(&b1[c4]);
#pragma unroll
        for (int i = 0; i < 8; i++) {
            float4 v;
            v.x = tanhf(hsum(acc[i][0]) + bb.x);
            v.y = tanhf(hsum(acc[i][1]) + bb.y);
            v.z = tanhf(hsum(acc[i][2]) + bb.z);
            v.w = tanhf(hsum(acc[i][3]) + bb.w);
            *reinterpret_cast<float4*>(&h1[(rg + 4 * i) * HD + c4]) = v;
        }
    }
    __syncthreads();

    // L2 + backward seed: dbuf = (1 - tanh^2(h1@W2 + b2)) * W3   (= d2)
    gemm2<HD>(h1, W2, acc, c4, rg);
    {
        float4 bb = ld4(&b2[c4]);
        float4 w3 = ld4(&W3[c4]);
#pragma unroll
        for (int i = 0; i < 8; i++) {
            float4 v;
            v.x = tanhf(hsum(acc[i][0]) + bb.x);
            v.y = tanhf(hsum(acc[i][1]) + bb.y);
            v.z = tanhf(hsum(acc[i][2]) + bb.z);
            v.w = tanhf(hsum(acc[i][3]) + bb.w);
            v.x = (1.f - v.x * v.x) * w3.x;
            v.y = (1.f - v.y * v.y) * w3.y;
            v.z = (1.f - v.z * v.z) * w3.z;
            v.w = (1.f - v.w * v.w) * w3.w;
            *reinterpret_cast<float4*>(&dbuf[(rg + 4 * i) * HD + c4]) = v;
        }
    }
    __syncthreads();

    // B2: h1 <- (dbuf @ W2T) * (1 - h1^2)
    gemm2<HD>(dbuf, g_W2T, acc, c4, rg);
#pragma unroll
    for (int i = 0; i < 8; i++) {
        float4* p = reinterpret_cast<float4*>(&h1[(rg + 4 * i) * HD + c4]);
        float4 h = *p;
        float4 v;
        v.x = hsum(acc[i][0]) * (1.f - h.x * h.x);
        v.y = hsum(acc[i][1]) * (1.f - h.y * h.y);
        v.z = hsum(acc[i][2]) * (1.f - h.z * h.z);
        v.w = hsum(acc[i][3]) * (1.f - h.w * h.w);
        *p = v;
    }
    __syncthreads();

    // B1: h0 <- (h1 @ W1T) * (1 - h0^2)
    gemm2<HD>(h1, g_W1T, acc, c4, rg);
#pragma unroll
    for (int i = 0; i < 8; i++) {
        float4* p = reinterpret_cast<float4*>(&h0[(rg + 4 * i) * HD + c4]);
        float4 h = *p;
        float4 v;
        v.x = hsum(acc[i][0]) * (1.f - h.x * h.x);
        v.y = hsum(acc[i][1]) * (1.f - h.y * h.y);
        v.z = hsum(acc[i][2]) * (1.f - h.z * h.z);
        v.w = hsum(acc[i][3]) * (1.f - h.w * h.w);
        *p = v;
    }
    __syncthreads();

    // Final: gradH[r][c] = sum_k d0[r][k] * W0T[k][c], c in [0,64). Scalar path.
    {
        const int fcl = tid & 63;       // output col
        const int frg = tid >> 6;       // rows frg + 8*i, i=0..3
        float accf[4] = {0.f, 0.f, 0.f, 0.f};
        for (int k = 0; k < HD; k += 4) {
            float av[4][4];
#pragma unroll
            for (int i = 0; i < 4; i++) {
                float4 a4 = ld4(&h0[(frg + 8 * i) * HD + k]);
                av[i][0] = a4.x; av[i][1] = a4.y; av[i][2] = a4.z; av[i][3] = a4.w;
            }
#pragma unroll
            for (int kk = 0; kk < 4; kk++) {
                float w = g_W0T[(k + kk) * DD + fcl];
#pragma unroll
                for (int i = 0; i < 4; i++)
                    accf[i] += av[i][kk] * w;
            }
        }
        const int oc = (fcl + 32) & 63;
        const float sgn = (fcl < 32) ? -1.f : 1.f;
#pragma unroll
        for (int i = 0; i < 4; i++) {
            long rgl = base_row + frg + 8 * i;
            out[rgl * DD + oc] = sgn * accf[i];
        }
    }
}

extern "C" void kernel_launch(void* const* d_in, const int* in_sizes, int n_in,
                              void* d_out, int out_size)
{
    // metadata order: t, x, W0, b0, W1, b1, W2, b2, W3, b3
    const float* x  = (const float*)d_in[1];
    const float* W0 = (const float*)d_in[2];
    const float* b0 = (const float*)d_in[3];
    const float* W1 = (const float*)d_in[4];
    const float* b1 = (const float*)d_in[5];
    const float* W2 = (const float*)d_in[6];
    const float* b2 = (const float*)d_in[7];
    const float* W3 = (const float*)d_in[8];
    float* out = (float*)d_out;

    float *pW1T, *pW2T, *pW0T;
    cudaGetSymbolAddress((void**)&pW1T, g_W1T);
    cudaGetSymbolAddress((void**)&pW2T, g_W2T);
    cudaGetSymbolAddress((void**)&pW0T, g_W0T);

    dim3 tb(32, 8);
    tr_kernel<<<dim3(HD / 32, HD / 32), tb>>>(W1, pW1T, HD, HD);
    tr_kernel<<<dim3(HD / 32, HD / 32), tb>>>(W2, pW2T, HD, HD);
    tr_kernel<<<dim3(HD / 32, DD / 32), tb>>>(W0, pW0T, DD, HD);

    const int B = in_sizes[1] / DD;  // 65536
    const int smem_bytes = 3 * ROWS * HD * sizeof(float);  // 196608

    cudaFuncSetAttribute(hnn_fused_kernel,
                         cudaFuncAttributeMaxDynamicSharedMemorySize, smem_bytes);

    hnn_fused_kernel<<<B / ROWS, NT, smem_bytes>>>(
        x, W0, b0, W1, b1, W2, b2, W3, out);
}

// round 7
// speedup vs baseline: 1.6627x; 1.6627x over previous
#include <cuda_runtime.h>

#define HD 512
#define DD 64
#define ROWS 32
#define NT 512

// Transposed weights (filled by transpose kernels each launch).
__device__ float g_W1T[HD * HD];   // W1T[k][c] = W1[c][k]
__device__ float g_W2T[HD * HD];   // W2T[k][c] = W2[c][k]
__device__ float g_W0T[HD * DD];   // W0T[h][d] = W0[d][h]

__device__ __forceinline__ float4 ld4(const float* __restrict__ p) {
    return *reinterpret_cast<const float4*>(p);
}

// Tiled transpose: in[R][C] -> out[C][R]
__global__ void tr_kernel(const float* __restrict__ in, float* __restrict__ out,
                          int R, int C) {
    __shared__ float t[32][33];
    int x = blockIdx.x * 32 + threadIdx.x;
    int y = blockIdx.y * 32 + threadIdx.y;
#pragma unroll
    for (int dy = 0; dy < 32; dy += 8)
        if (y + dy < R && x < C)
            t[threadIdx.y + dy][threadIdx.x] = in[(y + dy) * C + x];
    __syncthreads();
    int xo = blockIdx.y * 32 + threadIdx.x;
    int yo = blockIdx.x * 32 + threadIdx.y;
#pragma unroll
    for (int dy = 0; dy < 32; dy += 8)
        if (yo + dy < C && xo < R)
            out[(yo + dy) * R + xo] = t[threadIdx.x][threadIdx.y + dy];
}

// GEMM tile: 8 rows (rg+4i, i=0..7) x 1 float4-col (c4).
// prev: smem [ROWS][K] (warp-broadcast LDS.128); W: global [K][HD] coalesced.
// Per 4-k step: 4 LDG.128 + 8 LDS.128 + 128 FFMA; W float4 reused by 8 rows.
template<int K>
__device__ __forceinline__ void gemm_tile(
    const float* __restrict__ prev, const float* __restrict__ W,
    float4 acc[8], int c4, int rg)
{
#pragma unroll
    for (int i = 0; i < 8; i++)
        acc[i] = make_float4(0.f, 0.f, 0.f, 0.f);

#pragma unroll 2
    for (int k = 0; k < K; k += 4) {
        float4 w0 = ld4(&W[(k + 0) * HD + c4]);
        float4 w1 = ld4(&W[(k + 1) * HD + c4]);
        float4 w2 = ld4(&W[(k + 2) * HD + c4]);
        float4 w3 = ld4(&W[(k + 3) * HD + c4]);
#pragma unroll
        for (int i = 0; i < 8; i++) {
            float4 a4 = ld4(&prev[(rg + 4 * i) * K + k]);  // broadcast within warp
            acc[i].x += a4.x * w0.x; acc[i].y += a4.x * w0.y;
            acc[i].z += a4.x * w0.z; acc[i].w += a4.x * w0.w;
            acc[i].x += a4.y * w1.x; acc[i].y += a4.y * w1.y;
            acc[i].z += a4.y * w1.z; acc[i].w += a4.y * w1.w;
            acc[i].x += a4.z * w2.x; acc[i].y += a4.z * w2.y;
            acc[i].z += a4.z * w2.z; acc[i].w += a4.z * w2.w;
            acc[i].x += a4.w * w3.x; acc[i].y += a4.w * w3.y;
            acc[i].z += a4.w * w3.z; acc[i].w += a4.w * w3.w;
        }
    }
}

__global__ void __launch_bounds__(NT, 1)
hnn_fused_kernel(
    const float* __restrict__ x,
    const float* __restrict__ W0, const float* __restrict__ b0,
    const float* __restrict__ W1, const float* __restrict__ b1,
    const float* __restrict__ W2, const float* __restrict__ b2,
    const float* __restrict__ W3,
    float* __restrict__ out)
{
    extern __shared__ float smem[];
    float* h0   = smem;                 // [32][512]
    float* h1   = smem + ROWS * HD;     // [32][512]
    float* dbuf = smem + 2 * ROWS * HD; // [32][512], first 2048 floats alias xs
    float* xs   = dbuf;                 // [32][64]

    const int tid = threadIdx.x;
    const int cl = tid & 127;           // float4-col index (0..127)
    const int c4 = cl * 4;              // scalar col base
    const int rg = tid >> 7;            // rows rg + 4*i, i=0..7
    const long base_row = (long)blockIdx.x * ROWS;

    // load x tile: 512 float4, one per thread (coalesced)
    {
        const float4* xg = reinterpret_cast<const float4*>(x + base_row * DD);
        reinterpret_cast<float4*>(xs)[tid] = xg[tid];
    }
    __syncthreads();

    float4 acc[8];

    // L0: h0 = tanh(xs @ W0 + b0)
    gemm_tile<DD>(xs, W0, acc, c4, rg);
    {
        float4 bb = ld4(&b0[c4]);
#pragma unroll
        for (int i = 0; i < 8; i++) {
            float4 v;
            v.x = tanhf(acc[i].x + bb.x);
            v.y = tanhf(acc[i].y + bb.y);
            v.z = tanhf(acc[i].z + bb.z);
            v.w = tanhf(acc[i].w + bb.w);
            *reinterpret_cast<float4*>(&h0[(rg + 4 * i) * HD + c4]) = v;
        }
    }
    __syncthreads();

    // L1: h1 = tanh(h0 @ W1 + b1)
    gemm_tile<HD>(h0, W1, acc, c4, rg);
    {
        float4 bb = ld4(&b1[c4]);
#pragma unroll
        for (int i = 0; i < 8; i++) {
            float4 v;
            v.x = tanhf(acc[i].x + bb.x);
            v.y = tanhf(acc[i].y + bb.y);
            v.z = tanhf(acc[i].z + bb.z);
            v.w = tanhf(acc[i].w + bb.w);
            *reinterpret_cast<float4*>(&h1[(rg + 4 * i) * HD + c4]) = v;
        }
    }
    __syncthreads();

    // L2 + backward seed: dbuf = (1 - tanh^2(h1@W2 + b2)) * W3   (= d2)
    gemm_tile<HD>(h1, W2, acc, c4, rg);
    {
        float4 bb = ld4(&b2[c4]);
        float4 w3 = ld4(&W3[c4]);
#pragma unroll
        for (int i = 0; i < 8; i++) {
            float4 v;
            v.x = tanhf(acc[i].x + bb.x);
            v.y = tanhf(acc[i].y + bb.y);
            v.z = tanhf(acc[i].z + bb.z);
            v.w = tanhf(acc[i].w + bb.w);
            v.x = (1.f - v.x * v.x) * w3.x;
            v.y = (1.f - v.y * v.y) * w3.y;
            v.z = (1.f - v.z * v.z) * w3.z;
            v.w = (1.f - v.w * v.w) * w3.w;
            *reinterpret_cast<float4*>(&dbuf[(rg + 4 * i) * HD + c4]) = v;
        }
    }
    __syncthreads();

    // B2: h1 <- (dbuf @ W2T) * (1 - h1^2)   (in-place, own positions only)
    gemm_tile<HD>(dbuf, g_W2T, acc, c4, rg);
#pragma unroll
    for (int i = 0; i < 8; i++) {
        float4* p = reinterpret_cast<float4*>(&h1[(rg + 4 * i) * HD + c4]);
        float4 h = *p;
        float4 v;
        v.x = acc[i].x * (1.f - h.x * h.x);
        v.y = acc[i].y * (1.f - h.y * h.y);
        v.z = acc[i].z * (1.f - h.z * h.z);
        v.w = acc[i].w * (1.f - h.w * h.w);
        *p = v;
    }
    __syncthreads();

    // B1: h0 <- (h1 @ W1T) * (1 - h0^2)
    gemm_tile<HD>(h1, g_W1T, acc, c4, rg);
#pragma unroll
    for (int i = 0; i < 8; i++) {
        float4* p = reinterpret_cast<float4*>(&h0[(rg + 4 * i) * HD + c4]);
        float4 h = *p;
        float4 v;
        v.x = acc[i].x * (1.f - h.x * h.x);
        v.y = acc[i].y * (1.f - h.y * h.y);
        v.z = acc[i].z * (1.f - h.z * h.z);
        v.w = acc[i].w * (1.f - h.w * h.w);
        *p = v;
    }
    __syncthreads();

    // Final: gradH[r][c] = sum_k d0[r][k] * W0T[k][c], c in [0,64)
    {
        const int fcl = tid & 63;       // output col
        const int frg = tid >> 6;       // rows frg + 8*i, i=0..3
        float accf[4] = {0.f, 0.f, 0.f, 0.f};
        for (int k = 0; k < HD; k += 4) {
            float av[4][4];
#pragma unroll
            for (int i = 0; i < 4; i++) {
                float4 a4 = ld4(&h0[(frg + 8 * i) * HD + k]);
                av[i][0] = a4.x; av[i][1] = a4.y; av[i][2] = a4.z; av[i][3] = a4.w;
            }
#pragma unroll
            for (int kk = 0; kk < 4; kk++) {
                float w = g_W0T[(k + kk) * DD + fcl];
#pragma unroll
                for (int i = 0; i < 4; i++)
                    accf[i] += av[i][kk] * w;
            }
        }
        // symplectic: out[:,fcl+32] = -gradH[:,fcl] (fcl<32); out[:,fcl-32] = gradH[:,fcl]
        const int oc = (fcl + 32) & 63;
        const float sgn = (fcl < 32) ? -1.f : 1.f;
#pragma unroll
        for (int i = 0; i < 4; i++) {
            long rgl = base_row + frg + 8 * i;
            out[rgl * DD + oc] = sgn * accf[i];
        }
    }
}

extern "C" void kernel_launch(void* const* d_in, const int* in_sizes, int n_in,
                              void* d_out, int out_size)
{
    // metadata order: t, x, W0, b0, W1, b1, W2, b2, W3, b3
    const float* x  = (const float*)d_in[1];
    const float* W0 = (const float*)d_in[2];
    const float* b0 = (const float*)d_in[3];
    const float* W1 = (const float*)d_in[4];
    const float* b1 = (const float*)d_in[5];
    const float* W2 = (const float*)d_in[6];
    const float* b2 = (const float*)d_in[7];
    const float* W3 = (const float*)d_in[8];
    float* out = (float*)d_out;

    float *pW1T, *pW2T, *pW0T;
    cudaGetSymbolAddress((void**)&pW1T, g_W1T);
    cudaGetSymbolAddress((void**)&pW2T, g_W2T);
    cudaGetSymbolAddress((void**)&pW0T, g_W0T);

    dim3 tb(32, 8);
    tr_kernel<<<dim3(HD / 32, HD / 32), tb>>>(W1, pW1T, HD, HD);
    tr_kernel<<<dim3(HD / 32, HD / 32), tb>>>(W2, pW2T, HD, HD);
    tr_kernel<<<dim3(HD / 32, DD / 32), tb>>>(W0, pW0T, DD, HD);

    const int B = in_sizes[1] / DD;  // 65536
    const int smem_bytes = 3 * ROWS * HD * sizeof(float);  // 196608

    cudaFuncSetAttribute(hnn_fused_kernel,
                         cudaFuncAttributeMaxDynamicSharedMemorySize, smem_bytes);

    hnn_fused_kernel<<<B / ROWS, NT, smem_bytes>>>(
        x, W0, b0, W1, b1, W2, b2, W3, out);
}